// round 1
// baseline (speedup 1.0000x reference)
#include <cuda_runtime.h>
#include <cuda_bf16.h>
#include <math.h>

// ---------------------------------------------------------------------------
// Problem constants
// ---------------------------------------------------------------------------
#define Bc   2
#define Tc   2048
#define Cc   2048
#define NH   16
#define NKV  8
#define HD   128
#define QKVW 4096            // (NH + 2*NKV) * HD
#define NREP 2

// ---------------------------------------------------------------------------
// Scratch (device globals; no allocation allowed)
// ---------------------------------------------------------------------------
__device__ float g_qkv[(size_t)Bc * Tc * QKVW];        // 16.7M floats
__device__ float g_q[(size_t)Bc * NH * Tc * HD];       // 8.4M
__device__ float g_k[(size_t)Bc * NKV * Tc * HD];      // 4.2M
__device__ float g_v[(size_t)Bc * NKV * Tc * HD];      // 4.2M
__device__ float g_y[(size_t)Bc * Tc * Cc];            // 8.4M

// ---------------------------------------------------------------------------
// Tiled fp32 GEMM: C[M,N] = A[M,K] @ B[K,N], all row-major.
// BM=BN=128, BK=16, 256 threads, 8x8 per-thread micro-tile.
// Requires M%128==0, N%128==0, K%16==0 (true for all shapes here).
// ---------------------------------------------------------------------------
#define GBM 128
#define GBN 128
#define GBK 16

__global__ __launch_bounds__(256) void gemm_f32(
    const float* __restrict__ A, const float* __restrict__ B,
    float* __restrict__ C, int M, int N, int K)
{
    __shared__ float As[GBK][GBM];
    __shared__ float Bs[GBK][GBN];

    const int bx = blockIdx.x;          // N tile
    const int by = blockIdx.y;          // M tile
    const int tid = threadIdx.x;
    const int tx = tid & 15;
    const int ty = tid >> 4;

    float acc[8][8];
#pragma unroll
    for (int i = 0; i < 8; i++)
#pragma unroll
        for (int j = 0; j < 8; j++) acc[i][j] = 0.f;

    const float* Ab = A + (size_t)by * GBM * K;
    const float* Bb = B + (size_t)bx * GBN;

    for (int k0 = 0; k0 < K; k0 += GBK) {
        // load A tile (128x16) transposed into As[k][m]
#pragma unroll
        for (int i = 0; i < 2; i++) {
            int idx  = tid + i * 256;       // 0..511
            int row  = idx >> 2;            // 0..127
            int col4 = idx & 3;             // 0..3
            float4 v = *(const float4*)(Ab + (size_t)row * K + k0 + col4 * 4);
            As[col4 * 4 + 0][row] = v.x;
            As[col4 * 4 + 1][row] = v.y;
            As[col4 * 4 + 2][row] = v.z;
            As[col4 * 4 + 3][row] = v.w;
        }
        // load B tile (16x128)
#pragma unroll
        for (int i = 0; i < 2; i++) {
            int idx  = tid + i * 256;
            int row  = idx >> 5;            // 0..15
            int col4 = idx & 31;            // 0..31
            float4 v = *(const float4*)(Bb + (size_t)(k0 + row) * N + col4 * 4);
            *(float4*)&Bs[row][col4 * 4] = v;
        }
        __syncthreads();

#pragma unroll
        for (int kk = 0; kk < GBK; kk++) {
            float a[8], b[8];
#pragma unroll
            for (int i = 0; i < 8; i++) a[i] = As[kk][ty * 8 + i];
#pragma unroll
            for (int j = 0; j < 8; j++) b[j] = Bs[kk][tx * 8 + j];
#pragma unroll
            for (int i = 0; i < 8; i++)
#pragma unroll
                for (int j = 0; j < 8; j++)
                    acc[i][j] += a[i] * b[j];
        }
        __syncthreads();
    }

    float* Cb = C + (size_t)(by * GBM + ty * 8) * N + bx * GBN + tx * 8;
#pragma unroll
    for (int i = 0; i < 8; i++) {
#pragma unroll
        for (int j = 0; j < 8; j += 4) {
            float4 v = make_float4(acc[i][j], acc[i][j + 1], acc[i][j + 2], acc[i][j + 3]);
            *(float4*)(Cb + (size_t)i * N + j) = v;
        }
    }
}

// ---------------------------------------------------------------------------
// RoPE + split/transpose: g_qkv [B*T, 4096] ->
//   g_q [B,NH,T,HD] (rotated), g_k [B,NKV,T,HD] (rotated), g_v [B,NKV,T,HD]
// ---------------------------------------------------------------------------
#define NQP ((size_t)Bc * Tc * NH * (HD / 2))     // 4,194,304 q pairs
#define NKP ((size_t)Bc * Tc * NKV * (HD / 2))    // 2,097,152 k pairs
#define NVE ((size_t)Bc * Tc * NKV * HD)          // 4,194,304 v elems

__global__ __launch_bounds__(256) void rope_split_kernel(
    const float* __restrict__ fcos, const float* __restrict__ fsin)
{
    size_t idx = (size_t)blockIdx.x * blockDim.x + threadIdx.x;
    if (idx < NQP) {
        int p = idx & 63;
        int h = (idx >> 6) & (NH - 1);
        int t = (int)((idx >> 6) / NH) & (Tc - 1);
        int b = (int)(idx / ((size_t)64 * NH * Tc));
        const float* row = g_qkv + ((size_t)(b * Tc + t)) * QKVW + h * HD;
        float x0 = row[2 * p], x1 = row[2 * p + 1];
        float c = fcos[t * 64 + p], s = fsin[t * 64 + p];
        float* o = g_q + (((size_t)(b * NH + h)) * Tc + t) * HD;
        o[2 * p]     = x0 * c - x1 * s;
        o[2 * p + 1] = x0 * s + x1 * c;
    } else if (idx < NQP + NKP) {
        size_t j = idx - NQP;
        int p = j & 63;
        int g = (j >> 6) & (NKV - 1);
        int t = (int)((j >> 6) / NKV) & (Tc - 1);
        int b = (int)(j / ((size_t)64 * NKV * Tc));
        const float* row = g_qkv + ((size_t)(b * Tc + t)) * QKVW + NH * HD + g * HD;
        float x0 = row[2 * p], x1 = row[2 * p + 1];
        float c = fcos[t * 64 + p], s = fsin[t * 64 + p];
        float* o = g_k + (((size_t)(b * NKV + g)) * Tc + t) * HD;
        o[2 * p]     = x0 * c - x1 * s;
        o[2 * p + 1] = x0 * s + x1 * c;
    } else if (idx < NQP + NKP + NVE) {
        size_t j = idx - NQP - NKP;
        int d = j & (HD - 1);
        int g = (int)(j >> 7) & (NKV - 1);
        int t = (int)((j >> 7) / NKV) & (Tc - 1);
        int b = (int)(j / ((size_t)HD * NKV * Tc));
        g_v[(((size_t)(b * NKV + g)) * Tc + t) * HD + d] =
            g_qkv[((size_t)(b * Tc + t)) * QKVW + (NH + NKV) * HD + g * HD + d];
    }
}

// ---------------------------------------------------------------------------
// Flash attention (causal), fp32.
// CTA: one 64-query block of one head. 256 threads = 8 warps; warp w owns
// query rows [8w, 8w+8). Lane owns score cols {lane, lane+32} and O dims
// {lane, lane+32, lane+64, lane+96}. Online softmax in registers.
// Output written directly in [B, T, NH*HD] layout (the y-transpose is free).
// ---------------------------------------------------------------------------
struct SmemAttn {
    float Qs[64][128];
    float Ks[64][132];   // +4 pad: conflict-free float4 column reads
    float Vs[64][132];
    float Ps[64][65];
};

__global__ __launch_bounds__(256, 1) void flash_kernel()
{
    extern __shared__ unsigned char smem_u[];
    SmemAttn& sm = *reinterpret_cast<SmemAttn*>(smem_u);

    const int qb = blockIdx.x;          // query block (0..31)
    const int h  = blockIdx.y;          // q head (0..15)
    const int b  = blockIdx.z;
    const int g  = h >> 1;              // kv head
    const int tid = threadIdx.x;
    const int lane = tid & 31;
    const int w = tid >> 5;
    const int wrow = w * 8;

    const float* Qg = g_q + (((size_t)(b * NH + h)) * Tc + (size_t)qb * 64) * HD;
    const float* Kg = g_k + ((size_t)(b * NKV + g)) * Tc * HD;
    const float* Vg = g_v + ((size_t)(b * NKV + g)) * Tc * HD;

    // Load Q block: 64x128 = 2048 float4, 8 per thread.
#pragma unroll
    for (int i = 0; i < 8; i++) {
        int idx = tid + i * 256;
        int row = idx >> 5;
        int c4  = idx & 31;
        *(float4*)&sm.Qs[row][c4 * 4] = *(const float4*)(Qg + (size_t)row * HD + c4 * 4);
    }

    float m[8], l[8], o[8][4];
#pragma unroll
    for (int r = 0; r < 8; r++) {
        m[r] = -INFINITY; l[r] = 0.f;
#pragma unroll
        for (int di = 0; di < 4; di++) o[r][di] = 0.f;
    }

    const float scale = 0.08838834764831845f;   // 1/sqrt(128)

    for (int kb = 0; kb <= qb; kb++) {
        __syncthreads();   // prior-iter smem reads done (also fences Q load)
#pragma unroll
        for (int i = 0; i < 8; i++) {
            int idx = tid + i * 256;
            int row = idx >> 5;
            int c4  = idx & 31;
            *(float4*)&sm.Ks[row][c4 * 4] =
                *(const float4*)(Kg + ((size_t)(kb * 64 + row)) * HD + c4 * 4);
            *(float4*)&sm.Vs[row][c4 * 4] =
                *(const float4*)(Vg + ((size_t)(kb * 64 + row)) * HD + c4 * 4);
        }
        __syncthreads();

        // S = Q K^T for this tile
        float s0[8], s1[8];
#pragma unroll
        for (int r = 0; r < 8; r++) { s0[r] = 0.f; s1[r] = 0.f; }
#pragma unroll 4
        for (int k = 0; k < HD; k += 4) {
            float4 k0 = *(const float4*)&sm.Ks[lane][k];
            float4 k1 = *(const float4*)&sm.Ks[lane + 32][k];
#pragma unroll
            for (int r = 0; r < 8; r++) {
                float4 q = *(const float4*)&sm.Qs[wrow + r][k];
                s0[r] += q.x * k0.x + q.y * k0.y + q.z * k0.z + q.w * k0.w;
                s1[r] += q.x * k1.x + q.y * k1.y + q.z * k1.z + q.w * k1.w;
            }
        }

        // online softmax update
        const bool diag = (kb == qb);
        const int jg0 = kb * 64 + lane;
        const int jg1 = jg0 + 32;
#pragma unroll
        for (int r = 0; r < 8; r++) {
            int ig = qb * 64 + wrow + r;
            float v0 = s0[r] * scale;
            float v1 = s1[r] * scale;
            if (diag) {
                if (jg0 > ig) v0 = -INFINITY;
                if (jg1 > ig) v1 = -INFINITY;
            }
            float mx = fmaxf(v0, v1);
#pragma unroll
            for (int off = 16; off > 0; off >>= 1)
                mx = fmaxf(mx, __shfl_xor_sync(0xffffffffu, mx, off));
            float mnew  = fmaxf(m[r], mx);
            float alpha = __expf(m[r] - mnew);
            float p0 = __expf(v0 - mnew);
            float p1 = __expf(v1 - mnew);
            float ps = p0 + p1;
#pragma unroll
            for (int off = 16; off > 0; off >>= 1)
                ps += __shfl_xor_sync(0xffffffffu, ps, off);
            l[r] = l[r] * alpha + ps;
            m[r] = mnew;
#pragma unroll
            for (int di = 0; di < 4; di++) o[r][di] *= alpha;
            sm.Ps[wrow + r][lane]      = p0;
            sm.Ps[wrow + r][lane + 32] = p1;
        }
        __syncwarp();

        // O += P V
        for (int j = 0; j < 64; j++) {
            float v0 = sm.Vs[j][lane];
            float v1 = sm.Vs[j][lane + 32];
            float v2 = sm.Vs[j][lane + 64];
            float v3 = sm.Vs[j][lane + 96];
#pragma unroll
            for (int r = 0; r < 8; r++) {
                float p = sm.Ps[wrow + r][j];
                o[r][0] += p * v0;
                o[r][1] += p * v1;
                o[r][2] += p * v2;
                o[r][3] += p * v3;
            }
        }
    }

    // epilogue: y[b, t, h*HD + d] = O / l
#pragma unroll
    for (int r = 0; r < 8; r++) {
        int t = qb * 64 + wrow + r;
        float inv = 1.0f / l[r];
        float* yrow = g_y + ((size_t)(b * Tc + t)) * Cc + h * HD;
        yrow[lane]      = o[r][0] * inv;
        yrow[lane + 32] = o[r][1] * inv;
        yrow[lane + 64] = o[r][2] * inv;
        yrow[lane + 96] = o[r][3] * inv;
    }
}

// ---------------------------------------------------------------------------
// Launch
// ---------------------------------------------------------------------------
extern "C" void kernel_launch(void* const* d_in, const int* in_sizes, int n_in,
                              void* d_out, int out_size)
{
    const float* x      = (const float*)d_in[0];
    const float* w_attn = (const float*)d_in[1];
    const float* w_proj = (const float*)d_in[2];
    const float* fcos   = (const float*)d_in[3];
    const float* fsin   = (const float*)d_in[4];
    float* out = (float*)d_out;

    // resolve scratch symbols (host-side query; not a stream op, capture-safe)
    void *p_qkv, *p_y;
    cudaGetSymbolAddress(&p_qkv, g_qkv);
    cudaGetSymbolAddress(&p_y, g_y);

    // opt-in smem for the flash kernel (idempotent, capture-safe)
    cudaFuncSetAttribute(flash_kernel, cudaFuncAttributeMaxDynamicSharedMemorySize,
                         (int)sizeof(SmemAttn));

    // 1) QKV projection: [4096,2048] @ [2048,4096]
    gemm_f32<<<dim3(QKVW / GBN, (Bc * Tc) / GBM), 256>>>(
        x, w_attn, (float*)p_qkv, Bc * Tc, QKVW, Cc);

    // 2) RoPE + split/transpose
    {
        size_t total = NQP + NKP + NVE;
        int blocks = (int)((total + 255) / 256);
        rope_split_kernel<<<blocks, 256>>>(fcos, fsin);
    }

    // 3) causal flash attention
    flash_kernel<<<dim3(Tc / 64, NH, Bc), 256, sizeof(SmemAttn)>>>();

    // 4) output projection: [4096,2048] @ [2048,2048]
    gemm_f32<<<dim3(Cc / GBN, (Bc * Tc) / GBM), 256>>>(
        (const float*)p_y, w_proj, out, Bc * Tc, Cc, Cc);
}

// round 10
// speedup vs baseline: 3.6946x; 3.6946x over previous
#include <cuda_runtime.h>
#include <cuda_fp16.h>
#include <math.h>
#include <stdint.h>
#include <string.h>

// ---------------------------------------------------------------------------
// Problem constants
// ---------------------------------------------------------------------------
#define Bc   2
#define Tc   2048
#define Cc   2048
#define NH   16
#define NKV  8
#define HD   128
#define QKVW 4096            // (NH + 2*NKV) * HD

// ---------------------------------------------------------------------------
// Scratch (device globals; no allocation allowed)
// ---------------------------------------------------------------------------
__device__ float  g_qkv[(size_t)Bc * Tc * QKVW];
__device__ __half g_qh [(size_t)Bc * NH  * Tc * HD];   // rope'd, pre-scaled by 1/sqrt(HD)
__device__ __half g_kh [(size_t)Bc * NKV * Tc * HD];   // rope'd
__device__ __half g_vh [(size_t)Bc * NKV * Tc * HD];
__device__ float  g_y  [(size_t)Bc * Tc * Cc];

// ---------------------------------------------------------------------------
// helpers
// ---------------------------------------------------------------------------
__device__ __forceinline__ uint32_t h2_as_u32(__half2 h) {
    uint32_t u;
    memcpy(&u, &h, 4);
    return u;
}

__device__ __forceinline__ uint32_t f2tf32(float f) {
    uint32_t u;
    asm("cvt.rna.tf32.f32 %0, %1;" : "=r"(u) : "f"(f));
    return u;
}

__device__ __forceinline__ void mma_tf32(float* c, const uint32_t* a, uint32_t b0, uint32_t b1) {
    asm volatile(
        "mma.sync.aligned.m16n8k8.row.col.f32.tf32.tf32.f32 "
        "{%0,%1,%2,%3}, {%4,%5,%6,%7}, {%8,%9}, {%0,%1,%2,%3};"
        : "+f"(c[0]), "+f"(c[1]), "+f"(c[2]), "+f"(c[3])
        : "r"(a[0]), "r"(a[1]), "r"(a[2]), "r"(a[3]), "r"(b0), "r"(b1));
}

__device__ __forceinline__ void mma_f16(float* c, const uint32_t* a, uint32_t b0, uint32_t b1) {
    asm volatile(
        "mma.sync.aligned.m16n8k16.row.col.f32.f16.f16.f32 "
        "{%0,%1,%2,%3}, {%4,%5,%6,%7}, {%8,%9}, {%0,%1,%2,%3};"
        : "+f"(c[0]), "+f"(c[1]), "+f"(c[2]), "+f"(c[3])
        : "r"(a[0]), "r"(a[1]), "r"(a[2]), "r"(a[3]), "r"(b0), "r"(b1));
}

__device__ __forceinline__ void ldsm4t(uint32_t* r, uint32_t addr) {
    asm volatile(
        "ldmatrix.sync.aligned.m8n8.x4.trans.shared.b16 {%0,%1,%2,%3}, [%4];"
        : "=r"(r[0]), "=r"(r[1]), "=r"(r[2]), "=r"(r[3]) : "r"(addr));
}

// ---------------------------------------------------------------------------
// TF32 GEMM: C[M,N] = A[M,K] @ B[K,N], row-major fp32 in/out.
// BM=BN=128, BK=32. 8 warps: warp grid 2(M)x4(N), warp tile 64x32.
// ---------------------------------------------------------------------------
__global__ __launch_bounds__(256, 2) void gemm_tf32(
    const float* __restrict__ A, const float* __restrict__ B,
    float* __restrict__ C, int M, int N, int K)
{
    __shared__ float As[128][36];   // [m][k], pad->stride 36: frag loads conflict-free
    __shared__ float Bs[32][132];   // [k][n], pad->stride 132

    const int tid  = threadIdx.x;
    const int lane = tid & 31;
    const int wid  = tid >> 5;
    const int wm   = wid & 1;       // 0..1  (64-row slab)
    const int wn   = wid >> 1;      // 0..3  (32-col slab)
    const int g    = lane >> 2;
    const int tig  = lane & 3;

    float acc[4][4][4];
#pragma unroll
    for (int i = 0; i < 4; i++)
#pragma unroll
        for (int j = 0; j < 4; j++)
#pragma unroll
            for (int e = 0; e < 4; e++) acc[i][j][e] = 0.f;

    const float* Ab = A + (size_t)blockIdx.y * 128 * K;
    const float* Bb = B + (size_t)blockIdx.x * 128;

    for (int k0 = 0; k0 < K; k0 += 32) {
        // A tile 128x32
#pragma unroll
        for (int i = 0; i < 4; i++) {
            int idx = tid + i * 256;
            int r = idx >> 3, c = idx & 7;
            float4 v = *(const float4*)(Ab + (size_t)r * K + k0 + c * 4);
            As[r][c * 4 + 0] = __uint_as_float(f2tf32(v.x));
            As[r][c * 4 + 1] = __uint_as_float(f2tf32(v.y));
            As[r][c * 4 + 2] = __uint_as_float(f2tf32(v.z));
            As[r][c * 4 + 3] = __uint_as_float(f2tf32(v.w));
        }
        // B tile 32x128
#pragma unroll
        for (int i = 0; i < 4; i++) {
            int idx = tid + i * 256;
            int r = idx >> 5, c = idx & 31;
            float4 v = *(const float4*)(Bb + (size_t)(k0 + r) * N + c * 4);
            Bs[r][c * 4 + 0] = __uint_as_float(f2tf32(v.x));
            Bs[r][c * 4 + 1] = __uint_as_float(f2tf32(v.y));
            Bs[r][c * 4 + 2] = __uint_as_float(f2tf32(v.z));
            Bs[r][c * 4 + 3] = __uint_as_float(f2tf32(v.w));
        }
        __syncthreads();

#pragma unroll
        for (int kb = 0; kb < 4; kb++) {
            uint32_t af[4][4], bf[4][2];
#pragma unroll
            for (int i = 0; i < 4; i++) {
                int r = wm * 64 + i * 16;
                af[i][0] = __float_as_uint(As[r + g    ][kb * 8 + tig]);
                af[i][1] = __float_as_uint(As[r + g + 8][kb * 8 + tig]);
                af[i][2] = __float_as_uint(As[r + g    ][kb * 8 + tig + 4]);
                af[i][3] = __float_as_uint(As[r + g + 8][kb * 8 + tig + 4]);
            }
#pragma unroll
            for (int j = 0; j < 4; j++) {
                int c = wn * 32 + j * 8;
                bf[j][0] = __float_as_uint(Bs[kb * 8 + tig    ][c + g]);
                bf[j][1] = __float_as_uint(Bs[kb * 8 + tig + 4][c + g]);
            }
#pragma unroll
            for (int i = 0; i < 4; i++)
#pragma unroll
                for (int j = 0; j < 4; j++)
                    mma_tf32(acc[i][j], af[i], bf[j][0], bf[j][1]);
        }
        __syncthreads();
    }

    // epilogue
#pragma unroll
    for (int i = 0; i < 4; i++) {
        int r = blockIdx.y * 128 + wm * 64 + i * 16 + g;
#pragma unroll
        for (int j = 0; j < 4; j++) {
            int c = blockIdx.x * 128 + wn * 32 + j * 8 + 2 * tig;
            *(float2*)(C + (size_t)r * N + c)       = make_float2(acc[i][j][0], acc[i][j][1]);
            *(float2*)(C + (size_t)(r + 8) * N + c) = make_float2(acc[i][j][2], acc[i][j][3]);
        }
    }
}

// ---------------------------------------------------------------------------
// RoPE + split/transpose + fp16 convert.
// q gets the 1/sqrt(HD) scale folded in.
// ---------------------------------------------------------------------------
#define NQP ((size_t)Bc * Tc * NH  * (HD / 2))
#define NKP ((size_t)Bc * Tc * NKV * (HD / 2))
#define NVP ((size_t)Bc * Tc * NKV * (HD / 2))

__global__ __launch_bounds__(256) void rope_split_kernel(
    const float* __restrict__ fcos, const float* __restrict__ fsin)
{
    const float scale = 0.08838834764831845f;   // 1/sqrt(128)
    size_t idx = (size_t)blockIdx.x * blockDim.x + threadIdx.x;
    if (idx < NQP) {
        int p = idx & 63;
        int h = (idx >> 6) & (NH - 1);
        int t = (int)((idx >> 6) / NH) & (Tc - 1);
        int b = (int)(idx / ((size_t)64 * NH * Tc));
        const float* row = g_qkv + ((size_t)(b * Tc + t)) * QKVW + h * HD;
        float x0 = row[2 * p], x1 = row[2 * p + 1];
        float c = fcos[t * 64 + p], s = fsin[t * 64 + p];
        __half2* o = (__half2*)(g_qh + (((size_t)(b * NH + h)) * Tc + t) * HD);
        o[p] = __floats2half2_rn((x0 * c - x1 * s) * scale, (x0 * s + x1 * c) * scale);
    } else if (idx < NQP + NKP) {
        size_t j = idx - NQP;
        int p = j & 63;
        int gk = (j >> 6) & (NKV - 1);
        int t = (int)((j >> 6) / NKV) & (Tc - 1);
        int b = (int)(j / ((size_t)64 * NKV * Tc));
        const float* row = g_qkv + ((size_t)(b * Tc + t)) * QKVW + NH * HD + gk * HD;
        float x0 = row[2 * p], x1 = row[2 * p + 1];
        float c = fcos[t * 64 + p], s = fsin[t * 64 + p];
        __half2* o = (__half2*)(g_kh + (((size_t)(b * NKV + gk)) * Tc + t) * HD);
        o[p] = __floats2half2_rn(x0 * c - x1 * s, x0 * s + x1 * c);
    } else if (idx < NQP + NKP + NVP) {
        size_t j = idx - NQP - NKP;
        int p = j & 63;
        int gk = (j >> 6) & (NKV - 1);
        int t = (int)((j >> 6) / NKV) & (Tc - 1);
        int b = (int)(j / ((size_t)64 * NKV * Tc));
        const float* row = g_qkv + ((size_t)(b * Tc + t)) * QKVW + (NH + NKV) * HD + gk * HD;
        __half2* o = (__half2*)(g_vh + (((size_t)(b * NKV + gk)) * Tc + t) * HD);
        o[p] = __floats2half2_rn(row[2 * p], row[2 * p + 1]);
    }
}

// ---------------------------------------------------------------------------
// Flash attention (causal), f16 mma, fp32 softmax/accum.
// CTA: 128 queries x 1 head. 8 warps x 16 rows. KV blocks of 64.
// ---------------------------------------------------------------------------
#define QSTR 136            // half-element row stride (conflict-free)

struct FSmem {
    __half Q[128][QSTR];
    __half K[64][QSTR];
    __half V[64][QSTR];
};

__global__ __launch_bounds__(256, 1) void flash16()
{
    extern __shared__ unsigned char su[];
    FSmem& sm = *reinterpret_cast<FSmem*>(su);

    // heavy q-blocks first (more kv work) to reduce wave-tail imbalance
    const int bx = gridDim.x - 1 - blockIdx.x;
    const int h  = blockIdx.y;
    const int b  = blockIdx.z;
    const int gk = h >> 1;
    const int tid  = threadIdx.x;
    const int lane = tid & 31;
    const int w    = tid >> 5;
    const int g    = lane >> 2;
    const int tig  = lane & 3;

    const __half* Qg = g_qh + (((size_t)(b * NH + h)) * Tc + (size_t)bx * 128) * HD;
    const __half* Kg = g_kh + ((size_t)(b * NKV + gk)) * Tc * HD;
    const __half* Vg = g_vh + ((size_t)(b * NKV + gk)) * Tc * HD;

    // load Q tile 128x128 halves
#pragma unroll
    for (int i = 0; i < 8; i++) {
        int idx = tid + i * 256;
        int r = idx >> 4, c = idx & 15;
        *(uint4*)&sm.Q[r][c * 8] = *(const uint4*)(Qg + (size_t)r * HD + c * 8);
    }
    __syncthreads();

    // Q fragments, register-resident for whole CTA
    uint32_t qf[8][4];
    const int r0 = w * 16;
#pragma unroll
    for (int kc = 0; kc < 8; kc++) {
        qf[kc][0] = *(const uint32_t*)&sm.Q[r0 + g    ][kc * 16 + 2 * tig];
        qf[kc][1] = *(const uint32_t*)&sm.Q[r0 + g + 8][kc * 16 + 2 * tig];
        qf[kc][2] = *(const uint32_t*)&sm.Q[r0 + g    ][kc * 16 + 2 * tig + 8];
        qf[kc][3] = *(const uint32_t*)&sm.Q[r0 + g + 8][kc * 16 + 2 * tig + 8];
    }

    float o[16][4];
#pragma unroll
    for (int i = 0; i < 16; i++)
#pragma unroll
        for (int e = 0; e < 4; e++) o[i][e] = 0.f;
    float m0 = -INFINITY, m1 = -INFINITY, l0 = 0.f, l1 = 0.f;

    const int row0 = bx * 128 + w * 16 + g;     // global q row (lane rows: row0, row0+8)
    const int nkb  = 2 * bx + 2;

    for (int kb = 0; kb < nkb; kb++) {
        __syncthreads();
#pragma unroll
        for (int i = 0; i < 4; i++) {
            int idx = tid + i * 256;
            int r = idx >> 4, c = idx & 15;
            *(uint4*)&sm.K[r][c * 8] = *(const uint4*)(Kg + ((size_t)(kb * 64 + r)) * HD + c * 8);
            *(uint4*)&sm.V[r][c * 8] = *(const uint4*)(Vg + ((size_t)(kb * 64 + r)) * HD + c * 8);
        }
        __syncthreads();

        // S = Q K^T (fp32 accum)
        float s[8][4];
#pragma unroll
        for (int nt = 0; nt < 8; nt++)
#pragma unroll
            for (int e = 0; e < 4; e++) s[nt][e] = 0.f;

#pragma unroll
        for (int kc = 0; kc < 8; kc++) {
#pragma unroll
            for (int nt = 0; nt < 8; nt++) {
                uint32_t b0 = *(const uint32_t*)&sm.K[nt * 8 + g][kc * 16 + 2 * tig];
                uint32_t b1 = *(const uint32_t*)&sm.K[nt * 8 + g][kc * 16 + 2 * tig + 8];
                mma_f16(s[nt], qf[kc], b0, b1);
            }
        }

        // causal mask (only the last two blocks of this CTA need it)
        if (kb >= 2 * bx) {
#pragma unroll
            for (int nt = 0; nt < 8; nt++) {
                int c0 = kb * 64 + nt * 8 + 2 * tig;
                if (c0     > row0)     s[nt][0] = -INFINITY;
                if (c0 + 1 > row0)     s[nt][1] = -INFINITY;
                if (c0     > row0 + 8) s[nt][2] = -INFINITY;
                if (c0 + 1 > row0 + 8) s[nt][3] = -INFINITY;
            }
        }

        // online softmax
        float mx0 = -INFINITY, mx1 = -INFINITY;
#pragma unroll
        for (int nt = 0; nt < 8; nt++) {
            mx0 = fmaxf(mx0, fmaxf(s[nt][0], s[nt][1]));
            mx1 = fmaxf(mx1, fmaxf(s[nt][2], s[nt][3]));
        }
        mx0 = fmaxf(mx0, __shfl_xor_sync(0xffffffffu, mx0, 1));
        mx0 = fmaxf(mx0, __shfl_xor_sync(0xffffffffu, mx0, 2));
        mx1 = fmaxf(mx1, __shfl_xor_sync(0xffffffffu, mx1, 1));
        mx1 = fmaxf(mx1, __shfl_xor_sync(0xffffffffu, mx1, 2));

        float nm0 = fmaxf(m0, mx0), nm1 = fmaxf(m1, mx1);
        float a0 = __expf(m0 - nm0), a1 = __expf(m1 - nm1);
        m0 = nm0; m1 = nm1;

        float sum0 = 0.f, sum1 = 0.f;
        uint32_t ph0[8], ph1[8];   // P halves: row g / row g+8
#pragma unroll
        for (int nt = 0; nt < 8; nt++) {
            float p0 = __expf(s[nt][0] - nm0);
            float p1 = __expf(s[nt][1] - nm0);
            float p2 = __expf(s[nt][2] - nm1);
            float p3 = __expf(s[nt][3] - nm1);
            sum0 += p0 + p1;
            sum1 += p2 + p3;
            ph0[nt] = h2_as_u32(__floats2half2_rn(p0, p1));
            ph1[nt] = h2_as_u32(__floats2half2_rn(p2, p3));
        }
        sum0 += __shfl_xor_sync(0xffffffffu, sum0, 1);
        sum0 += __shfl_xor_sync(0xffffffffu, sum0, 2);
        sum1 += __shfl_xor_sync(0xffffffffu, sum1, 1);
        sum1 += __shfl_xor_sync(0xffffffffu, sum1, 2);
        l0 = l0 * a0 + sum0;
        l1 = l1 * a1 + sum1;

#pragma unroll
        for (int nt = 0; nt < 16; nt++) {
            o[nt][0] *= a0; o[nt][1] *= a0;
            o[nt][2] *= a1; o[nt][3] *= a1;
        }

        // O += P V
#pragma unroll
        for (int kk = 0; kk < 4; kk++) {
            uint32_t pa[4] = { ph0[2 * kk], ph1[2 * kk], ph0[2 * kk + 1], ph1[2 * kk + 1] };
            uint32_t base = (uint32_t)__cvta_generic_to_shared(
                &sm.V[kk * 16 + (lane & 15)][(lane >> 4) * 8]);
#pragma unroll
            for (int np = 0; np < 8; np++) {
                uint32_t vf[4];
                ldsm4t(vf, base + np * 16 * 2);
                mma_f16(o[2 * np],     pa, vf[0], vf[1]);
                mma_f16(o[2 * np + 1], pa, vf[2], vf[3]);
            }
        }
    }

    // epilogue: y[b, t, h*HD + d] = O / l
    const float il0 = 1.0f / l0;
    const float il1 = 1.0f / l1;
#pragma unroll
    for (int nt = 0; nt < 16; nt++) {
        int col = h * HD + nt * 8 + 2 * tig;
        float* y0 = g_y + ((size_t)(b * Tc + row0)) * Cc + col;
        float* y1 = g_y + ((size_t)(b * Tc + row0 + 8)) * Cc + col;
        *(float2*)y0 = make_float2(o[nt][0] * il0, o[nt][1] * il0);
        *(float2*)y1 = make_float2(o[nt][2] * il1, o[nt][3] * il1);
    }
}

// ---------------------------------------------------------------------------
// Launch
// ---------------------------------------------------------------------------
extern "C" void kernel_launch(void* const* d_in, const int* in_sizes, int n_in,
                              void* d_out, int out_size)
{
    const float* x      = (const float*)d_in[0];
    const float* w_attn = (const float*)d_in[1];
    const float* w_proj = (const float*)d_in[2];
    const float* fcos   = (const float*)d_in[3];
    const float* fsin   = (const float*)d_in[4];
    float* out = (float*)d_out;

    void *p_qkv, *p_y;
    cudaGetSymbolAddress(&p_qkv, g_qkv);
    cudaGetSymbolAddress(&p_y, g_y);

    cudaFuncSetAttribute(flash16, cudaFuncAttributeMaxDynamicSharedMemorySize,
                         (int)sizeof(FSmem));

    // 1) QKV projection (tf32 tensor cores): [4096,2048] @ [2048,4096]
    gemm_tf32<<<dim3(QKVW / 128, (Bc * Tc) / 128), 256>>>(
        x, w_attn, (float*)p_qkv, Bc * Tc, QKVW, Cc);

    // 2) RoPE + split + fp16 convert (scale folded into q)
    {
        size_t total = NQP + NKP + NVP;
        int blocks = (int)((total + 255) / 256);
        rope_split_kernel<<<blocks, 256>>>(fcos, fsin);
    }

    // 3) causal flash attention (f16 tensor cores)
    flash16<<<dim3(Tc / 128, NH, Bc), 256, sizeof(FSmem)>>>();

    // 4) output projection (tf32): [4096,2048] @ [2048,2048]
    gemm_tf32<<<dim3(Cc / 128, (Bc * Tc) / 128), 256>>>(
        (const float*)p_y, w_proj, out, Bc * Tc, Cc, Cc);
}

// round 17
// speedup vs baseline: 3.7981x; 1.0280x over previous
#include <cuda_runtime.h>
#include <cuda_fp16.h>
#include <math.h>
#include <stdint.h>
#include <string.h>

// ---------------------------------------------------------------------------
// Problem constants
// ---------------------------------------------------------------------------
#define Bc   2
#define Tc   2048
#define Cc   2048
#define NH   16
#define NKV  8
#define HD   128
#define QKVW 4096            // (NH + 2*NKV) * HD

// ---------------------------------------------------------------------------
// Scratch (device globals; no allocation allowed)
// ---------------------------------------------------------------------------
__device__ float  g_qkv[(size_t)Bc * Tc * QKVW];
__device__ __half g_qh [(size_t)Bc * NH  * Tc * HD];   // rope'd, pre-scaled by 1/sqrt(HD)
__device__ __half g_kh [(size_t)Bc * NKV * Tc * HD];   // rope'd
__device__ __half g_vh [(size_t)Bc * NKV * Tc * HD];
__device__ float  g_y  [(size_t)Bc * Tc * Cc];

// ---------------------------------------------------------------------------
// helpers
// ---------------------------------------------------------------------------
__device__ __forceinline__ uint32_t h2_as_u32(__half2 h) {
    uint32_t u;
    memcpy(&u, &h, 4);
    return u;
}

__device__ __forceinline__ uint32_t f2tf32(float f) {
    uint32_t u;
    asm("cvt.rna.tf32.f32 %0, %1;" : "=r"(u) : "f"(f));
    return u;
}

__device__ __forceinline__ void mma_tf32(float* c, const uint32_t* a, uint32_t b0, uint32_t b1) {
    asm volatile(
        "mma.sync.aligned.m16n8k8.row.col.f32.tf32.tf32.f32 "
        "{%0,%1,%2,%3}, {%4,%5,%6,%7}, {%8,%9}, {%0,%1,%2,%3};"
        : "+f"(c[0]), "+f"(c[1]), "+f"(c[2]), "+f"(c[3])
        : "r"(a[0]), "r"(a[1]), "r"(a[2]), "r"(a[3]), "r"(b0), "r"(b1));
}

__device__ __forceinline__ void mma_f16(float* c, const uint32_t* a, uint32_t b0, uint32_t b1) {
    asm volatile(
        "mma.sync.aligned.m16n8k16.row.col.f32.f16.f16.f32 "
        "{%0,%1,%2,%3}, {%4,%5,%6,%7}, {%8,%9}, {%0,%1,%2,%3};"
        : "+f"(c[0]), "+f"(c[1]), "+f"(c[2]), "+f"(c[3])
        : "r"(a[0]), "r"(a[1]), "r"(a[2]), "r"(a[3]), "r"(b0), "r"(b1));
}

// non-transposed ldmatrix x4 (B-frags for Q*K^T)
__device__ __forceinline__ void ldsm4(uint32_t* r, uint32_t addr) {
    asm volatile(
        "ldmatrix.sync.aligned.m8n8.x4.shared.b16 {%0,%1,%2,%3}, [%4];"
        : "=r"(r[0]), "=r"(r[1]), "=r"(r[2]), "=r"(r[3]) : "r"(addr));
}

// transposed ldmatrix x4 (V-frags for P*V)
__device__ __forceinline__ void ldsm4t(uint32_t* r, uint32_t addr) {
    asm volatile(
        "ldmatrix.sync.aligned.m8n8.x4.trans.shared.b16 {%0,%1,%2,%3}, [%4];"
        : "=r"(r[0]), "=r"(r[1]), "=r"(r[2]), "=r"(r[3]) : "r"(addr));
}

__device__ __forceinline__ void cp_async16(uint32_t smem_addr, const void* gptr) {
    asm volatile("cp.async.ca.shared.global [%0], [%1], 16;"
                 :: "r"(smem_addr), "l"(gptr) : "memory");
}
__device__ __forceinline__ void cp_commit() {
    asm volatile("cp.async.commit_group;" ::: "memory");
}
__device__ __forceinline__ void cp_wait_all() {
    asm volatile("cp.async.wait_group 0;" ::: "memory");
}

// ---------------------------------------------------------------------------
// TF32 GEMM: C[M,N] = A[M,K] @ B[K,N], row-major fp32 in/out.
// BM=BN=128, BK=32. 8 warps: warp grid 2(M)x4(N), warp tile 64x32.
// (unchanged from the validated R10 kernel)
// ---------------------------------------------------------------------------
__global__ __launch_bounds__(256, 2) void gemm_tf32(
    const float* __restrict__ A, const float* __restrict__ B,
    float* __restrict__ C, int M, int N, int K)
{
    __shared__ float As[128][36];   // [m][k], pad->stride 36: frag loads conflict-free
    __shared__ float Bs[32][132];   // [k][n], pad->stride 132

    const int tid  = threadIdx.x;
    const int lane = tid & 31;
    const int wid  = tid >> 5;
    const int wm   = wid & 1;       // 0..1  (64-row slab)
    const int wn   = wid >> 1;      // 0..3  (32-col slab)
    const int g    = lane >> 2;
    const int tig  = lane & 3;

    float acc[4][4][4];
#pragma unroll
    for (int i = 0; i < 4; i++)
#pragma unroll
        for (int j = 0; j < 4; j++)
#pragma unroll
            for (int e = 0; e < 4; e++) acc[i][j][e] = 0.f;

    const float* Ab = A + (size_t)blockIdx.y * 128 * K;
    const float* Bb = B + (size_t)blockIdx.x * 128;

    for (int k0 = 0; k0 < K; k0 += 32) {
        // A tile 128x32
#pragma unroll
        for (int i = 0; i < 4; i++) {
            int idx = tid + i * 256;
            int r = idx >> 3, c = idx & 7;
            float4 v = *(const float4*)(Ab + (size_t)r * K + k0 + c * 4);
            As[r][c * 4 + 0] = __uint_as_float(f2tf32(v.x));
            As[r][c * 4 + 1] = __uint_as_float(f2tf32(v.y));
            As[r][c * 4 + 2] = __uint_as_float(f2tf32(v.z));
            As[r][c * 4 + 3] = __uint_as_float(f2tf32(v.w));
        }
        // B tile 32x128
#pragma unroll
        for (int i = 0; i < 4; i++) {
            int idx = tid + i * 256;
            int r = idx >> 5, c = idx & 31;
            float4 v = *(const float4*)(Bb + (size_t)(k0 + r) * N + c * 4);
            Bs[r][c * 4 + 0] = __uint_as_float(f2tf32(v.x));
            Bs[r][c * 4 + 1] = __uint_as_float(f2tf32(v.y));
            Bs[r][c * 4 + 2] = __uint_as_float(f2tf32(v.z));
            Bs[r][c * 4 + 3] = __uint_as_float(f2tf32(v.w));
        }
        __syncthreads();

#pragma unroll
        for (int kb = 0; kb < 4; kb++) {
            uint32_t af[4][4], bf[4][2];
#pragma unroll
            for (int i = 0; i < 4; i++) {
                int r = wm * 64 + i * 16;
                af[i][0] = __float_as_uint(As[r + g    ][kb * 8 + tig]);
                af[i][1] = __float_as_uint(As[r + g + 8][kb * 8 + tig]);
                af[i][2] = __float_as_uint(As[r + g    ][kb * 8 + tig + 4]);
                af[i][3] = __float_as_uint(As[r + g + 8][kb * 8 + tig + 4]);
            }
#pragma unroll
            for (int j = 0; j < 4; j++) {
                int c = wn * 32 + j * 8;
                bf[j][0] = __float_as_uint(Bs[kb * 8 + tig    ][c + g]);
                bf[j][1] = __float_as_uint(Bs[kb * 8 + tig + 4][c + g]);
            }
#pragma unroll
            for (int i = 0; i < 4; i++)
#pragma unroll
                for (int j = 0; j < 4; j++)
                    mma_tf32(acc[i][j], af[i], bf[j][0], bf[j][1]);
        }
        __syncthreads();
    }

    // epilogue
#pragma unroll
    for (int i = 0; i < 4; i++) {
        int r = blockIdx.y * 128 + wm * 64 + i * 16 + g;
#pragma unroll
        for (int j = 0; j < 4; j++) {
            int c = blockIdx.x * 128 + wn * 32 + j * 8 + 2 * tig;
            *(float2*)(C + (size_t)r * N + c)       = make_float2(acc[i][j][0], acc[i][j][1]);
            *(float2*)(C + (size_t)(r + 8) * N + c) = make_float2(acc[i][j][2], acc[i][j][3]);
        }
    }
}

// ---------------------------------------------------------------------------
// RoPE + split/transpose + fp16 convert (unchanged).
// ---------------------------------------------------------------------------
#define NQP ((size_t)Bc * Tc * NH  * (HD / 2))
#define NKP ((size_t)Bc * Tc * NKV * (HD / 2))
#define NVP ((size_t)Bc * Tc * NKV * (HD / 2))

__global__ __launch_bounds__(256) void rope_split_kernel(
    const float* __restrict__ fcos, const float* __restrict__ fsin)
{
    const float scale = 0.08838834764831845f;   // 1/sqrt(128)
    size_t idx = (size_t)blockIdx.x * blockDim.x + threadIdx.x;
    if (idx < NQP) {
        int p = idx & 63;
        int h = (idx >> 6) & (NH - 1);
        int t = (int)((idx >> 6) / NH) & (Tc - 1);
        int b = (int)(idx / ((size_t)64 * NH * Tc));
        const float* row = g_qkv + ((size_t)(b * Tc + t)) * QKVW + h * HD;
        float x0 = row[2 * p], x1 = row[2 * p + 1];
        float c = fcos[t * 64 + p], s = fsin[t * 64 + p];
        __half2* o = (__half2*)(g_qh + (((size_t)(b * NH + h)) * Tc + t) * HD);
        o[p] = __floats2half2_rn((x0 * c - x1 * s) * scale, (x0 * s + x1 * c) * scale);
    } else if (idx < NQP + NKP) {
        size_t j = idx - NQP;
        int p = j & 63;
        int gk = (j >> 6) & (NKV - 1);
        int t = (int)((j >> 6) / NKV) & (Tc - 1);
        int b = (int)(j / ((size_t)64 * NKV * Tc));
        const float* row = g_qkv + ((size_t)(b * Tc + t)) * QKVW + NH * HD + gk * HD;
        float x0 = row[2 * p], x1 = row[2 * p + 1];
        float c = fcos[t * 64 + p], s = fsin[t * 64 + p];
        __half2* o = (__half2*)(g_kh + (((size_t)(b * NKV + gk)) * Tc + t) * HD);
        o[p] = __floats2half2_rn(x0 * c - x1 * s, x0 * s + x1 * c);
    } else if (idx < NQP + NKP + NVP) {
        size_t j = idx - NQP - NKP;
        int p = j & 63;
        int gk = (j >> 6) & (NKV - 1);
        int t = (int)((j >> 6) / NKV) & (Tc - 1);
        int b = (int)(j / ((size_t)64 * NKV * Tc));
        const float* row = g_qkv + ((size_t)(b * Tc + t)) * QKVW + (NH + NKV) * HD + gk * HD;
        __half2* o = (__half2*)(g_vh + (((size_t)(b * NKV + gk)) * Tc + t) * HD);
        o[p] = __floats2half2_rn(row[2 * p], row[2 * p + 1]);
    }
}

// ---------------------------------------------------------------------------
// Flash attention (causal), f16 mma, fp32 softmax/accum.
// CTA: 128 queries x 1 head. 8 warps x 16 rows. KV blocks of 64.
// R11: K-frags via ldmatrix.x4 (conflict-free), K/V double-buffered cp.async.
// ---------------------------------------------------------------------------
#define QSTR 136            // half-element row stride (conflict-free)

struct FSmem {
    __half Q[128][QSTR];        // 34816 B
    __half K[2][64][QSTR];      // 2 x 17408 B (ping-pong)
    __half V[2][64][QSTR];      // 2 x 17408 B
};

__global__ __launch_bounds__(256, 1) void flash16()
{
    extern __shared__ unsigned char su[];
    FSmem& sm = *reinterpret_cast<FSmem*>(su);

    // heavy q-blocks first (more kv work) to reduce wave-tail imbalance
    const int bx = gridDim.x - 1 - blockIdx.x;
    const int h  = blockIdx.y;
    const int b  = blockIdx.z;
    const int gk = h >> 1;
    const int tid  = threadIdx.x;
    const int lane = tid & 31;
    const int w    = tid >> 5;
    const int g    = lane >> 2;
    const int tig  = lane & 3;

    const __half* Qg = g_qh + (((size_t)(b * NH + h)) * Tc + (size_t)bx * 128) * HD;
    const __half* Kg = g_kh + ((size_t)(b * NKV + gk)) * Tc * HD;
    const __half* Vg = g_vh + ((size_t)(b * NKV + gk)) * Tc * HD;

    const int nkb = 2 * bx + 2;

    // KV async load: per buffer, 64 rows x 128 halves = 1024 x 16B; 4/thread each
    const int ldr = tid >> 4;          // 0..15 base row
    const int ldc = tid & 15;          // 0..15 16B chunk
    {
        // prefetch kb = 0 into buffer 0
#pragma unroll
        for (int i = 0; i < 4; i++) {
            int r = ldr + i * 16;
            cp_async16((uint32_t)__cvta_generic_to_shared(&sm.K[0][r][ldc * 8]),
                       Kg + (size_t)r * HD + ldc * 8);
            cp_async16((uint32_t)__cvta_generic_to_shared(&sm.V[0][r][ldc * 8]),
                       Vg + (size_t)r * HD + ldc * 8);
        }
        cp_commit();
    }

    // load Q tile 128x128 halves (overlaps with the cp.async above)
#pragma unroll
    for (int i = 0; i < 8; i++) {
        int idx = tid + i * 256;
        int r = idx >> 4, c = idx & 15;
        *(uint4*)&sm.Q[r][c * 8] = *(const uint4*)(Qg + (size_t)r * HD + c * 8);
    }
    __syncthreads();

    // Q fragments, register-resident for whole CTA
    uint32_t qf[8][4];
    const int r0 = w * 16;
#pragma unroll
    for (int kc = 0; kc < 8; kc++) {
        qf[kc][0] = *(const uint32_t*)&sm.Q[r0 + g    ][kc * 16 + 2 * tig];
        qf[kc][1] = *(const uint32_t*)&sm.Q[r0 + g + 8][kc * 16 + 2 * tig];
        qf[kc][2] = *(const uint32_t*)&sm.Q[r0 + g    ][kc * 16 + 2 * tig + 8];
        qf[kc][3] = *(const uint32_t*)&sm.Q[r0 + g + 8][kc * 16 + 2 * tig + 8];
    }

    float o[16][4];
#pragma unroll
    for (int i = 0; i < 16; i++)
#pragma unroll
        for (int e = 0; e < 4; e++) o[i][e] = 0.f;
    float m0 = -INFINITY, m1 = -INFINITY, l0 = 0.f, l1 = 0.f;

    const int row0 = bx * 128 + w * 16 + g;     // global q row (lane rows: row0, row0+8)

    // per-lane ldmatrix base offsets (quad q covers {b0,b1} x {nt,nt+1})
    const int lq = lane >> 3;                   // 0..3
    const int lr = lane & 7;                    // row within 8
    const uint32_t kfoff =
        (uint32_t)(((lq >> 1) * 8 + lr) * (QSTR * 2) + (lq & 1) * 16);

    for (int kb = 0; kb < nkb; kb++) {
        const int buf = kb & 1;

        cp_wait_all();
        __syncthreads();   // data for kb ready; all warps done reading other buffer

        // prefetch kb+1 into the other buffer (overlaps with compute below)
        if (kb + 1 < nkb) {
            const int nbuf = buf ^ 1;
#pragma unroll
            for (int i = 0; i < 4; i++) {
                int r = ldr + i * 16;
                cp_async16((uint32_t)__cvta_generic_to_shared(&sm.K[nbuf][r][ldc * 8]),
                           Kg + ((size_t)((kb + 1) * 64 + r)) * HD + ldc * 8);
                cp_async16((uint32_t)__cvta_generic_to_shared(&sm.V[nbuf][r][ldc * 8]),
                           Vg + ((size_t)((kb + 1) * 64 + r)) * HD + ldc * 8);
            }
            cp_commit();
        }

        // S = Q K^T (fp32 accum), K-frags via conflict-free ldmatrix.x4
        float s[8][4];
#pragma unroll
        for (int nt = 0; nt < 8; nt++)
#pragma unroll
            for (int e = 0; e < 4; e++) s[nt][e] = 0.f;

        const uint32_t kfbase =
            (uint32_t)__cvta_generic_to_shared(&sm.K[buf][0][0]) + kfoff;
#pragma unroll
        for (int kc = 0; kc < 8; kc++) {
#pragma unroll
            for (int nt = 0; nt < 8; nt += 2) {
                uint32_t kf[4];
                ldsm4(kf, kfbase + (uint32_t)(nt * (8 * QSTR * 2) + kc * 32));
                mma_f16(s[nt],     qf[kc], kf[0], kf[1]);
                mma_f16(s[nt + 1], qf[kc], kf[2], kf[3]);
            }
        }

        // causal mask (only the last two blocks of this CTA need it)
        if (kb >= 2 * bx) {
#pragma unroll
            for (int nt = 0; nt < 8; nt++) {
                int c0 = kb * 64 + nt * 8 + 2 * tig;
                if (c0     > row0)     s[nt][0] = -INFINITY;
                if (c0 + 1 > row0)     s[nt][1] = -INFINITY;
                if (c0     > row0 + 8) s[nt][2] = -INFINITY;
                if (c0 + 1 > row0 + 8) s[nt][3] = -INFINITY;
            }
        }

        // online softmax
        float mx0 = -INFINITY, mx1 = -INFINITY;
#pragma unroll
        for (int nt = 0; nt < 8; nt++) {
            mx0 = fmaxf(mx0, fmaxf(s[nt][0], s[nt][1]));
            mx1 = fmaxf(mx1, fmaxf(s[nt][2], s[nt][3]));
        }
        mx0 = fmaxf(mx0, __shfl_xor_sync(0xffffffffu, mx0, 1));
        mx0 = fmaxf(mx0, __shfl_xor_sync(0xffffffffu, mx0, 2));
        mx1 = fmaxf(mx1, __shfl_xor_sync(0xffffffffu, mx1, 1));
        mx1 = fmaxf(mx1, __shfl_xor_sync(0xffffffffu, mx1, 2));

        float nm0 = fmaxf(m0, mx0), nm1 = fmaxf(m1, mx1);
        float a0 = __expf(m0 - nm0), a1 = __expf(m1 - nm1);
        m0 = nm0; m1 = nm1;

        float sum0 = 0.f, sum1 = 0.f;
        uint32_t ph0[8], ph1[8];   // P halves: row g / row g+8
#pragma unroll
        for (int nt = 0; nt < 8; nt++) {
            float p0 = __expf(s[nt][0] - nm0);
            float p1 = __expf(s[nt][1] - nm0);
            float p2 = __expf(s[nt][2] - nm1);
            float p3 = __expf(s[nt][3] - nm1);
            sum0 += p0 + p1;
            sum1 += p2 + p3;
            ph0[nt] = h2_as_u32(__floats2half2_rn(p0, p1));
            ph1[nt] = h2_as_u32(__floats2half2_rn(p2, p3));
        }
        sum0 += __shfl_xor_sync(0xffffffffu, sum0, 1);
        sum0 += __shfl_xor_sync(0xffffffffu, sum0, 2);
        sum1 += __shfl_xor_sync(0xffffffffu, sum1, 1);
        sum1 += __shfl_xor_sync(0xffffffffu, sum1, 2);
        l0 = l0 * a0 + sum0;
        l1 = l1 * a1 + sum1;

#pragma unroll
        for (int nt = 0; nt < 16; nt++) {
            o[nt][0] *= a0; o[nt][1] *= a0;
            o[nt][2] *= a1; o[nt][3] *= a1;
        }

        // O += P V
#pragma unroll
        for (int kk = 0; kk < 4; kk++) {
            uint32_t pa[4] = { ph0[2 * kk], ph1[2 * kk], ph0[2 * kk + 1], ph1[2 * kk + 1] };
            uint32_t base = (uint32_t)__cvta_generic_to_shared(
                &sm.V[buf][kk * 16 + (lane & 15)][(lane >> 4) * 8]);
#pragma unroll
            for (int np = 0; np < 8; np++) {
                uint32_t vf[4];
                ldsm4t(vf, base + np * 16 * 2);
                mma_f16(o[2 * np],     pa, vf[0], vf[1]);
                mma_f16(o[2 * np + 1], pa, vf[2], vf[3]);
            }
        }
        __syncthreads();   // all warps done with buf before next iter overwrites it
    }

    // epilogue: y[b, t, h*HD + d] = O / l
    const float il0 = 1.0f / l0;
    const float il1 = 1.0f / l1;
#pragma unroll
    for (int nt = 0; nt < 16; nt++) {
        int col = h * HD + nt * 8 + 2 * tig;
        float* y0 = g_y + ((size_t)(b * Tc + row0)) * Cc + col;
        float* y1 = g_y + ((size_t)(b * Tc + row0 + 8)) * Cc + col;
        *(float2*)y0 = make_float2(o[nt][0] * il0, o[nt][1] * il0);
        *(float2*)y1 = make_float2(o[nt][2] * il1, o[nt][3] * il1);
    }
}

// ---------------------------------------------------------------------------
// Launch
// ---------------------------------------------------------------------------
extern "C" void kernel_launch(void* const* d_in, const int* in_sizes, int n_in,
                              void* d_out, int out_size)
{
    const float* x      = (const float*)d_in[0];
    const float* w_attn = (const float*)d_in[1];
    const float* w_proj = (const float*)d_in[2];
    const float* fcos   = (const float*)d_in[3];
    const float* fsin   = (const float*)d_in[4];
    float* out = (float*)d_out;

    void *p_qkv, *p_y;
    cudaGetSymbolAddress(&p_qkv, g_qkv);
    cudaGetSymbolAddress(&p_y, g_y);

    cudaFuncSetAttribute(flash16, cudaFuncAttributeMaxDynamicSharedMemorySize,
                         (int)sizeof(FSmem));

    // 1) QKV projection (tf32 tensor cores): [4096,2048] @ [2048,4096]
    gemm_tf32<<<dim3(QKVW / 128, (Bc * Tc) / 128), 256>>>(
        x, w_attn, (float*)p_qkv, Bc * Tc, QKVW, Cc);

    // 2) RoPE + split + fp16 convert (scale folded into q)
    {
        size_t total = NQP + NKP + NVP;
        int blocks = (int)((total + 255) / 256);
        rope_split_kernel<<<blocks, 256>>>(fcos, fsin);
    }

    // 3) causal flash attention (f16 tensor cores)
    flash16<<<dim3(Tc / 128, NH, Bc), 256, sizeof(FSmem)>>>();

    // 4) output projection (tf32): [4096,2048] @ [2048,2048]
    gemm_tf32<<<dim3(Cc / 128, (Bc * Tc) / 128), 256>>>(
        (const float*)p_y, w_proj, out, Bc * Tc, Cc, Cc);
}